// round 1
// baseline (speedup 1.0000x reference)
#include <cuda_runtime.h>
#include <math.h>

#define N_IMG   128
#define TCAP    33
#define TSTEPS  32
#define D_FEAT  400
#define W_EMB   512
#define H_DIM   1024
#define V_SIZE  10000
#define Z_DIM   4096    // 4*H
#define P_SPAT  16

// ---------------- static device scratch (no allocs allowed) ----------------
__device__ float d_AT   [N_IMG*P_SPAT*D_FEAT];   // features transposed -> [2048,400]
__device__ float d_Araw [N_IMG*P_SPAT*H_DIM];    // A_flat as [(n*16+p), h] = [2048,1024]
__device__ float d_xbuf [TSTEPS*N_IMG*W_EMB];    // gathered embeddings [4096,512]
__device__ float d_zbase[TSTEPS*N_IMG*Z_DIM];    // x@Wx + b, [4096,4096]
__device__ float d_hcur [N_IMG*H_DIM];
__device__ float d_ccur [N_IMG*H_DIM];
__device__ float d_attn [N_IMG*H_DIM];
__device__ float d_z    [N_IMG*Z_DIM];
__device__ float d_hs   [TSTEPS*N_IMG*H_DIM];    // [4096,1024]
__device__ float d_scores[TSTEPS*N_IMG*V_SIZE];  // [4096,10000]
__device__ float d_nll  [TSTEPS*N_IMG];

// ---------------- generic fp32 GEMM: C = A@B (+ A2@B2) (+Cinit) (+bias) ----
// BM=BN=64, BK=16, 256 threads, 4x4 micro-tile. M multiple of 64, K mult of 16.
__global__ void gemm64x64(const float* __restrict__ A,  const float* __restrict__ B,
                          const float* __restrict__ A2, const float* __restrict__ B2,
                          const float* __restrict__ Cinit, const float* __restrict__ bias,
                          float* __restrict__ C, int M, int N, int K, int K2)
{
    __shared__ __align__(16) float As[64*16];
    __shared__ __align__(16) float Bs[16*64];
    const int tid = threadIdx.x;
    const int tx = tid & 15, ty = tid >> 4;
    const int rowBase = blockIdx.y * 64;
    const int colBase = blockIdx.x * 64;

    float acc[4][4];
#pragma unroll
    for (int i = 0; i < 4; ++i)
#pragma unroll
        for (int j = 0; j < 4; ++j) acc[i][j] = 0.f;

    const int npass = A2 ? 2 : 1;
    for (int pass = 0; pass < npass; ++pass) {
        const float* Ap = pass ? A2 : A;
        const float* Bp = pass ? B2 : B;
        const int    Kc = pass ? K2 : K;
        for (int k0 = 0; k0 < Kc; k0 += 16) {
            // load A tile 64x16 (coalesced 16-float rows)
#pragma unroll
            for (int j = 0; j < 4; ++j) {
                int i = tid + j * 256;
                int r = i >> 4, c = i & 15;
                As[i] = Ap[(size_t)(rowBase + r) * Kc + k0 + c];
            }
            // load B tile 16x64 (coalesced, guard N)
#pragma unroll
            for (int j = 0; j < 4; ++j) {
                int i = tid + j * 256;
                int r = i >> 6, c = i & 63;
                int col = colBase + c;
                Bs[i] = (col < N) ? Bp[(size_t)(k0 + r) * N + col] : 0.f;
            }
            __syncthreads();
#pragma unroll
            for (int kk = 0; kk < 16; ++kk) {
                float a0 = As[(ty*4+0)*16 + kk];
                float a1 = As[(ty*4+1)*16 + kk];
                float a2 = As[(ty*4+2)*16 + kk];
                float a3 = As[(ty*4+3)*16 + kk];
                float4 bv = *reinterpret_cast<const float4*>(&Bs[kk*64 + tx*4]);
                acc[0][0] += a0*bv.x; acc[0][1] += a0*bv.y; acc[0][2] += a0*bv.z; acc[0][3] += a0*bv.w;
                acc[1][0] += a1*bv.x; acc[1][1] += a1*bv.y; acc[1][2] += a1*bv.z; acc[1][3] += a1*bv.w;
                acc[2][0] += a2*bv.x; acc[2][1] += a2*bv.y; acc[2][2] += a2*bv.z; acc[2][3] += a2*bv.w;
                acc[3][0] += a3*bv.x; acc[3][1] += a3*bv.y; acc[3][2] += a3*bv.z; acc[3][3] += a3*bv.w;
            }
            __syncthreads();
        }
    }

#pragma unroll
    for (int i = 0; i < 4; ++i) {
        int row = rowBase + ty*4 + i;
#pragma unroll
        for (int j = 0; j < 4; ++j) {
            int col = colBase + tx*4 + j;
            if (col < N) {
                float v = acc[i][j];
                if (Cinit) v += Cinit[(size_t)row * N + col];
                if (bias)  v += bias[col];
                C[(size_t)row * N + col] = v;
            }
        }
    }
}

// ---------------- misc small kernels ----------------
__global__ void transpose_feat(const float* __restrict__ f) {
    int idx = blockIdx.x * 256 + threadIdx.x;          // 2048*400
    if (idx >= N_IMG*P_SPAT*D_FEAT) return;
    int d = idx % D_FEAT;
    int r = idx / D_FEAT;
    int n = r >> 4, p = r & 15;
    d_AT[idx] = f[(size_t)n * (D_FEAT*P_SPAT) + d * P_SPAT + p];
}

__global__ void h0_kernel() {
    int idx = blockIdx.x * 256 + threadIdx.x;          // 128*1024
    int n = idx >> 10, h = idx & 1023;
    float s = 0.f;
#pragma unroll
    for (int p = 0; p < 16; ++p) s += d_Araw[(size_t)(n*16 + p) * H_DIM + h];
    s *= (1.f / 16.f);
    d_hcur[idx] = s;
    d_ccur[idx] = s;
}

__global__ void gather_embed(const int* __restrict__ cap, const float* __restrict__ Wemb) {
    int idx = blockIdx.x * 256 + threadIdx.x;          // 4096*512
    if (idx >= TSTEPS*N_IMG*W_EMB) return;
    int w = idx & (W_EMB - 1);
    int r = idx >> 9;
    int t = r >> 7, n = r & 127;
    int c = cap[n * TCAP + t];
    d_xbuf[idx] = Wemb[(size_t)c * W_EMB + w];
}

// one block per image n, 512 threads; each thread owns 2 h values
__global__ void attn_kernel() {
    const int n = blockIdx.x;
    const int tid = threadIdx.x;
    __shared__ float wsum[16][16];   // [warp][p]
    __shared__ float wsm[16];

    float av[2][16];
    float partial[16];
#pragma unroll
    for (int p = 0; p < 16; ++p) partial[p] = 0.f;

#pragma unroll
    for (int e = 0; e < 2; ++e) {
        int h = tid + e * 512;
        float hv = d_hcur[n * H_DIM + h];
#pragma unroll
        for (int p = 0; p < 16; ++p) {
            float a = d_Araw[(size_t)(n*16 + p) * H_DIM + h];
            av[e][p] = a;
            partial[p] += hv * a;
        }
    }
    int lane = tid & 31, warp = tid >> 5;
#pragma unroll
    for (int p = 0; p < 16; ++p) {
        float v = partial[p];
#pragma unroll
        for (int o = 16; o > 0; o >>= 1) v += __shfl_down_sync(0xFFFFFFFFu, v, o);
        if (lane == 0) wsum[warp][p] = v;
    }
    __syncthreads();
    if (tid == 0) {
        float s[16]; float m = -1e30f;
#pragma unroll
        for (int p = 0; p < 16; ++p) {
            float v = 0.f;
            for (int w = 0; w < 16; ++w) v += wsum[w][p];
            v *= 0.03125f;            // 1/sqrt(1024)
            s[p] = v;
            m = fmaxf(m, v);
        }
        float tot = 0.f;
#pragma unroll
        for (int p = 0; p < 16; ++p) { s[p] = expf(s[p] - m); tot += s[p]; }
        float inv = 1.f / tot;
#pragma unroll
        for (int p = 0; p < 16; ++p) wsm[p] = s[p] * inv;
    }
    __syncthreads();
    float w[16];
#pragma unroll
    for (int p = 0; p < 16; ++p) w[p] = wsm[p];
#pragma unroll
    for (int e = 0; e < 2; ++e) {
        int h = tid + e * 512;
        float s = 0.f;
#pragma unroll
        for (int p = 0; p < 16; ++p) s += w[p] * av[e][p];
        d_attn[n * H_DIM + h] = s;
    }
}

__device__ __forceinline__ float sigmoidf_(float x) { return 1.f / (1.f + expf(-x)); }

__global__ void lstm_pointwise(int t) {
    int idx = blockIdx.x * 256 + threadIdx.x;          // 128*1024
    int n = idx >> 10, h = idx & 1023;
    const float* zr = d_z + (size_t)n * Z_DIM;
    float ai = zr[h];
    float af = zr[h + 1024];
    float ao = zr[h + 2048];
    float ag = zr[h + 3072];
    float c  = sigmoidf_(af) * d_ccur[idx] + sigmoidf_(ai) * tanhf(ag);
    float hn = sigmoidf_(ao) * tanhf(c);
    d_ccur[idx] = c;
    d_hcur[idx] = hn;
    d_hs[(size_t)t * (N_IMG*H_DIM) + idx] = hn;
}

// one block per (t,n) row: streaming logsumexp over V + target score
__global__ void loss_rows(const int* __restrict__ cap) {
    const int r = blockIdx.x;           // 0..4095, r = t*128 + n
    const int t = r >> 7, n = r & 127;
    const int tid = threadIdx.x;
    const int tgt = cap[n * TCAP + t + 1];
    const float* row = d_scores + (size_t)r * V_SIZE;

    __shared__ float sm_t;
    __shared__ float mm[256], ss[256];

    float m = -1e30f, s = 0.f;
    for (int v = tid; v < V_SIZE; v += 256) {
        float x = row[v];
        if (v == tgt) sm_t = x;
        if (x > m) { s = s * expf(m - x) + 1.f; m = x; }
        else       { s += expf(x - m); }
    }
    mm[tid] = m; ss[tid] = s;
    __syncthreads();
    for (int o = 128; o > 0; o >>= 1) {
        if (tid < o) {
            float m2 = mm[tid + o], s2 = ss[tid + o];
            float M = fmaxf(mm[tid], m2);
            ss[tid] = ss[tid] * expf(mm[tid] - M) + s2 * expf(m2 - M);
            mm[tid] = M;
        }
        __syncthreads();
    }
    if (tid == 0) {
        float lse = logf(ss[0]) + mm[0];
        d_nll[r] = (tgt != 0) ? (lse - sm_t) : 0.f;
    }
}

__global__ void loss_final(float* __restrict__ out) {
    const int tid = threadIdx.x;
    __shared__ float sm[256];
    float s = 0.f;
    for (int i = tid; i < TSTEPS*N_IMG; i += 256) s += d_nll[i];
    sm[tid] = s;
    __syncthreads();
    for (int o = 128; o > 0; o >>= 1) {
        if (tid < o) sm[tid] += sm[tid + o];
        __syncthreads();
    }
    if (tid == 0) out[0] = sm[0] / (float)N_IMG;
}

// ---------------- launch ----------------
extern "C" void kernel_launch(void* const* d_in, const int* in_sizes, int n_in,
                              void* d_out, int out_size)
{
    const float* features = (const float*)d_in[0];
    const int*   captions = (const int*)  d_in[1];
    const float* W_embed  = (const float*)d_in[2];
    const float* W_proj   = (const float*)d_in[3];
    const float* b_proj   = (const float*)d_in[4];
    const float* Wx       = (const float*)d_in[5];
    const float* Wh       = (const float*)d_in[6];
    const float* Wattn    = (const float*)d_in[7];
    const float* b        = (const float*)d_in[8];
    const float* W_vocab  = (const float*)d_in[9];
    const float* b_vocab  = (const float*)d_in[10];
    float* out = (float*)d_out;

    float *pAT, *pAraw, *pxbuf, *pzbase, *phcur, *pattn, *pz, *phs, *pscores;
    cudaGetSymbolAddress((void**)&pAT,     d_AT);
    cudaGetSymbolAddress((void**)&pAraw,   d_Araw);
    cudaGetSymbolAddress((void**)&pxbuf,   d_xbuf);
    cudaGetSymbolAddress((void**)&pzbase,  d_zbase);
    cudaGetSymbolAddress((void**)&phcur,   d_hcur);
    cudaGetSymbolAddress((void**)&pattn,   d_attn);
    cudaGetSymbolAddress((void**)&pz,      d_z);
    cudaGetSymbolAddress((void**)&phs,     d_hs);
    cudaGetSymbolAddress((void**)&pscores, d_scores);

    // 1) transpose features -> [2048,400]
    transpose_feat<<<(N_IMG*P_SPAT*D_FEAT + 255)/256, 256>>>(features);

    // 2) Araw = AT @ W_proj + b_proj   [2048,1024]
    gemm64x64<<<dim3(H_DIM/64, (N_IMG*P_SPAT)/64), 256>>>(
        pAT, W_proj, nullptr, nullptr, nullptr, b_proj, pAraw,
        N_IMG*P_SPAT, H_DIM, D_FEAT, 0);

    // 3) h0 = mean over spatial; init h,c
    h0_kernel<<<(N_IMG*H_DIM)/256, 256>>>();

    // 4) gather embeddings -> xbuf [4096,512]
    gather_embed<<<(TSTEPS*N_IMG*W_EMB + 255)/256, 256>>>(captions, W_embed);

    // 5) zbase = xbuf @ Wx + b   [4096,4096]
    gemm64x64<<<dim3(Z_DIM/64, (TSTEPS*N_IMG)/64), 256>>>(
        pxbuf, Wx, nullptr, nullptr, nullptr, b, pzbase,
        TSTEPS*N_IMG, Z_DIM, W_EMB, 0);

    // 6) recurrence
    for (int t = 0; t < TSTEPS; ++t) {
        attn_kernel<<<N_IMG, 512>>>();
        gemm64x64<<<dim3(Z_DIM/64, N_IMG/64), 256>>>(
            phcur, Wh, pattn, Wattn,
            pzbase + (size_t)t * N_IMG * Z_DIM, nullptr, pz,
            N_IMG, Z_DIM, H_DIM, H_DIM);
        lstm_pointwise<<<(N_IMG*H_DIM)/256, 256>>>(t);
    }

    // 7) scores = hs @ W_vocab + b_vocab   [4096,10000]
    gemm64x64<<<dim3((V_SIZE + 63)/64, (TSTEPS*N_IMG)/64), 256>>>(
        phs, W_vocab, nullptr, nullptr, nullptr, b_vocab, pscores,
        TSTEPS*N_IMG, V_SIZE, H_DIM, 0);

    // 8) loss
    loss_rows<<<TSTEPS*N_IMG, 256>>>(captions);
    loss_final<<<1, 256>>>(out);
}

// round 2
// speedup vs baseline: 2.1617x; 2.1617x over previous
#include <cuda_runtime.h>
#include <math.h>
#include <stdint.h>

#define N_IMG   128
#define TCAP    33
#define TSTEPS  32
#define D_FEAT  400
#define W_EMB   512
#define H_DIM   1024
#define V_SIZE  10000
#define Z_DIM   4096    // 4*H
#define P_SPAT  16

// ---------------- static device scratch (no allocs allowed) ----------------
__device__ float d_AT   [N_IMG*P_SPAT*D_FEAT];   // features transposed -> [2048,400]
__device__ float d_Araw [N_IMG*P_SPAT*H_DIM];    // A_flat as [(n*16+p), h] = [2048,1024]
__device__ float d_xbuf [TSTEPS*N_IMG*W_EMB];    // gathered embeddings [4096,512]
__device__ float d_zbase[TSTEPS*N_IMG*Z_DIM];    // x@Wx + b, [4096,4096]
__device__ float d_hcur [N_IMG*H_DIM];
__device__ float d_ccur [N_IMG*H_DIM];
__device__ float d_attn [N_IMG*H_DIM];
__device__ float d_z    [N_IMG*Z_DIM];
__device__ float d_hs   [TSTEPS*N_IMG*H_DIM];    // [4096,1024]
__device__ float d_scores[TSTEPS*N_IMG*V_SIZE];  // [4096,10000]
__device__ float d_nll  [TSTEPS*N_IMG];

// ---------------- tf32 helpers ----------------
__device__ __forceinline__ uint32_t f2tf32(float x) {
    uint32_t r;
    asm("cvt.rna.tf32.f32 %0, %1;" : "=r"(r) : "f"(x));
    return r;
}
__device__ __forceinline__ uint4 f4_to_tf32(float4 v) {
    uint4 r;
    r.x = f2tf32(v.x); r.y = f2tf32(v.y); r.z = f2tf32(v.z); r.w = f2tf32(v.w);
    return r;
}
__device__ __forceinline__ void mma_tf32(float c[4], const uint32_t a[4], const uint32_t b[2]) {
    asm volatile(
        "mma.sync.aligned.m16n8k8.row.col.f32.tf32.tf32.f32 "
        "{%0,%1,%2,%3},{%4,%5,%6,%7},{%8,%9},{%0,%1,%2,%3};"
        : "+f"(c[0]), "+f"(c[1]), "+f"(c[2]), "+f"(c[3])
        : "r"(a[0]), "r"(a[1]), "r"(a[2]), "r"(a[3]), "r"(b[0]), "r"(b[1]));
}

// ---------------- tf32 tensor-core GEMM ----------------
// C[M,N] = A[M,K] @ B[K,N] (+ A2[M,K2] @ B2[K2,N]) (+ Cinit) (+ bias)
// BN=64, BK=32 fixed. 256 threads = 8 warps as WARPS_M x WARPS_N.
// M multiple of BM, K,K2 multiple of 32, N multiple of 4 (with guard).
template<int BM, int WARPS_M, int WARPS_N>
__global__ __launch_bounds__(256)
void gemm_tf32(const float* __restrict__ A,  const float* __restrict__ B,
               const float* __restrict__ A2, const float* __restrict__ B2,
               const float* __restrict__ Cinit, const float* __restrict__ bias,
               float* __restrict__ C, int M, int N, int K, int K2)
{
    constexpr int BN = 64, BK = 32;
    constexpr int WM = BM / WARPS_M;     // 32
    constexpr int WN = BN / WARPS_N;     // 32 or 16
    constexpr int MT = WM / 16;          // 2
    constexpr int NT = WN / 8;           // 4 or 2
    constexpr int AS_STR = 36;           // 36 mod 32 = 4 -> conflict-free frag loads
    constexpr int BS_STR = 72;           // 72 mod 32 = 8 -> conflict-free frag loads

    __shared__ __align__(16) uint32_t As[BM][AS_STR];
    __shared__ __align__(16) uint32_t Bs[BK][BS_STR];

    const int tid  = threadIdx.x;
    const int lane = tid & 31;
    const int warp = tid >> 5;
    const int wm   = warp / WARPS_N;
    const int wn   = warp % WARPS_N;
    const int rowBase = blockIdx.y * BM;
    const int colBase = blockIdx.x * BN;

    float acc[MT][NT][4] = {};

    const int nch1 = K >> 5;
    const int nch2 = A2 ? (K2 >> 5) : 0;
    const int nch  = nch1 + nch2;

    uint4 ra[BM / 32];
    uint4 rb[2];

    auto gload = [&](int ch) {
        const float* Ap; const float* Bp; int Kc, k0;
        if (ch < nch1) { Ap = A;  Bp = B;  Kc = K;  k0 = ch << 5; }
        else           { Ap = A2; Bp = B2; Kc = K2; k0 = (ch - nch1) << 5; }
#pragma unroll
        for (int p = 0; p < BM / 32; ++p) {
            int m  = (tid >> 3) + p * 32;
            int kg = (tid & 7) << 2;
            float4 v = *reinterpret_cast<const float4*>(
                Ap + (size_t)(rowBase + m) * Kc + k0 + kg);
            ra[p] = f4_to_tf32(v);
        }
#pragma unroll
        for (int p = 0; p < 2; ++p) {
            int kr = (tid >> 4) + p * 16;
            int n4 = (tid & 15) << 2;
            int col = colBase + n4;
            float4 v = make_float4(0.f, 0.f, 0.f, 0.f);
            if (col < N) v = *reinterpret_cast<const float4*>(
                Bp + (size_t)(k0 + kr) * N + col);
            rb[p] = f4_to_tf32(v);
        }
    };

    auto sstore = [&]() {
#pragma unroll
        for (int p = 0; p < BM / 32; ++p) {
            int m  = (tid >> 3) + p * 32;
            int kg = (tid & 7) << 2;
            *reinterpret_cast<uint4*>(&As[m][kg]) = ra[p];
        }
#pragma unroll
        for (int p = 0; p < 2; ++p) {
            int kr = (tid >> 4) + p * 16;
            int n4 = (tid & 15) << 2;
            *reinterpret_cast<uint4*>(&Bs[kr][n4]) = rb[p];
        }
    };

    gload(0);
    for (int ch = 0; ch < nch; ++ch) {
        __syncthreads();
        sstore();
        __syncthreads();
        if (ch + 1 < nch) gload(ch + 1);
#pragma unroll
        for (int kk = 0; kk < 4; ++kk) {
            const int kq = (kk << 3) + (lane & 3);
            uint32_t af[MT][4];
#pragma unroll
            for (int mt = 0; mt < MT; ++mt) {
                int r0 = wm * WM + mt * 16 + (lane >> 2);
                af[mt][0] = As[r0][kq];
                af[mt][1] = As[r0 + 8][kq];
                af[mt][2] = As[r0][kq + 4];
                af[mt][3] = As[r0 + 8][kq + 4];
            }
            uint32_t bf[NT][2];
#pragma unroll
            for (int nt = 0; nt < NT; ++nt) {
                int cb = wn * WN + nt * 8 + (lane >> 2);
                bf[nt][0] = Bs[kq][cb];
                bf[nt][1] = Bs[kq + 4][cb];
            }
#pragma unroll
            for (int mt = 0; mt < MT; ++mt)
#pragma unroll
                for (int nt = 0; nt < NT; ++nt)
                    mma_tf32(acc[mt][nt], af[mt], bf[nt]);
        }
    }

    // epilogue: acc -> C (float2 stores; cols within tile: 2*(lane&3), +1)
#pragma unroll
    for (int mt = 0; mt < MT; ++mt) {
        int r0 = rowBase + wm * WM + mt * 16 + (lane >> 2);
#pragma unroll
        for (int nt = 0; nt < NT; ++nt) {
            int col = colBase + wn * WN + nt * 8 + ((lane & 3) << 1);
            if (col < N) {
                float2 v0 = make_float2(acc[mt][nt][0], acc[mt][nt][1]);
                float2 v1 = make_float2(acc[mt][nt][2], acc[mt][nt][3]);
                if (Cinit) {
                    float2 c0 = *reinterpret_cast<const float2*>(Cinit + (size_t)r0 * N + col);
                    float2 c1 = *reinterpret_cast<const float2*>(Cinit + (size_t)(r0 + 8) * N + col);
                    v0.x += c0.x; v0.y += c0.y; v1.x += c1.x; v1.y += c1.y;
                }
                if (bias) {
                    float2 bv = *reinterpret_cast<const float2*>(bias + col);
                    v0.x += bv.x; v0.y += bv.y; v1.x += bv.x; v1.y += bv.y;
                }
                *reinterpret_cast<float2*>(C + (size_t)r0 * N + col) = v0;
                *reinterpret_cast<float2*>(C + (size_t)(r0 + 8) * N + col) = v1;
            }
        }
    }
}

// ---------------- fp32 fallback GEMM (proj only, K=400) ----------------
__global__ void gemm64x64(const float* __restrict__ A, const float* __restrict__ B,
                          const float* __restrict__ bias,
                          float* __restrict__ C, int M, int N, int K)
{
    __shared__ __align__(16) float As[64 * 16];
    __shared__ __align__(16) float Bs[16 * 64];
    const int tid = threadIdx.x;
    const int tx = tid & 15, ty = tid >> 4;
    const int rowBase = blockIdx.y * 64;
    const int colBase = blockIdx.x * 64;

    float acc[4][4] = {};

    for (int k0 = 0; k0 < K; k0 += 16) {
#pragma unroll
        for (int j = 0; j < 4; ++j) {
            int i = tid + j * 256;
            int r = i >> 4, c = i & 15;
            As[i] = A[(size_t)(rowBase + r) * K + k0 + c];
        }
#pragma unroll
        for (int j = 0; j < 4; ++j) {
            int i = tid + j * 256;
            int r = i >> 6, c = i & 63;
            int col = colBase + c;
            Bs[i] = (col < N) ? B[(size_t)(k0 + r) * N + col] : 0.f;
        }
        __syncthreads();
#pragma unroll
        for (int kk = 0; kk < 16; ++kk) {
            float a0 = As[(ty * 4 + 0) * 16 + kk];
            float a1 = As[(ty * 4 + 1) * 16 + kk];
            float a2 = As[(ty * 4 + 2) * 16 + kk];
            float a3 = As[(ty * 4 + 3) * 16 + kk];
            float4 bv = *reinterpret_cast<const float4*>(&Bs[kk * 64 + tx * 4]);
            acc[0][0] += a0 * bv.x; acc[0][1] += a0 * bv.y; acc[0][2] += a0 * bv.z; acc[0][3] += a0 * bv.w;
            acc[1][0] += a1 * bv.x; acc[1][1] += a1 * bv.y; acc[1][2] += a1 * bv.z; acc[1][3] += a1 * bv.w;
            acc[2][0] += a2 * bv.x; acc[2][1] += a2 * bv.y; acc[2][2] += a2 * bv.z; acc[2][3] += a2 * bv.w;
            acc[3][0] += a3 * bv.x; acc[3][1] += a3 * bv.y; acc[3][2] += a3 * bv.z; acc[3][3] += a3 * bv.w;
        }
        __syncthreads();
    }
#pragma unroll
    for (int i = 0; i < 4; ++i) {
        int row = rowBase + ty * 4 + i;
#pragma unroll
        for (int j = 0; j < 4; ++j) {
            int col = colBase + tx * 4 + j;
            if (col < N) {
                float v = acc[i][j];
                if (bias) v += bias[col];
                C[(size_t)row * N + col] = v;
            }
        }
    }
}

// ---------------- misc small kernels ----------------
__global__ void transpose_feat(const float* __restrict__ f) {
    int idx = blockIdx.x * 256 + threadIdx.x;          // 2048*400
    if (idx >= N_IMG * P_SPAT * D_FEAT) return;
    int d = idx % D_FEAT;
    int r = idx / D_FEAT;
    int n = r >> 4, p = r & 15;
    d_AT[idx] = f[(size_t)n * (D_FEAT * P_SPAT) + d * P_SPAT + p];
}

__global__ void h0_kernel() {
    int idx = blockIdx.x * 256 + threadIdx.x;          // 128*1024
    int n = idx >> 10, h = idx & 1023;
    float s = 0.f;
#pragma unroll
    for (int p = 0; p < 16; ++p) s += d_Araw[(size_t)(n * 16 + p) * H_DIM + h];
    s *= (1.f / 16.f);
    d_hcur[idx] = s;
    d_ccur[idx] = s;
}

__global__ void gather_embed(const int* __restrict__ cap, const float* __restrict__ Wemb) {
    int idx = blockIdx.x * 256 + threadIdx.x;          // 4096*512
    if (idx >= TSTEPS * N_IMG * W_EMB) return;
    int w = idx & (W_EMB - 1);
    int r = idx >> 9;
    int t = r >> 7, n = r & 127;
    int c = cap[n * TCAP + t];
    d_xbuf[idx] = Wemb[(size_t)c * W_EMB + w];
}

__device__ __forceinline__ float sigmoidf_(float x) { return 1.f / (1.f + expf(-x)); }

// attention only (used once, before the loop, from h0)
__global__ void attn_kernel() {
    const int n = blockIdx.x;
    const int tid = threadIdx.x;
    __shared__ float wsum[16][17];
    __shared__ float wsm[16];

    float av[2][16];
    float partial[16];
#pragma unroll
    for (int p = 0; p < 16; ++p) partial[p] = 0.f;

#pragma unroll
    for (int e = 0; e < 2; ++e) {
        int h = tid + e * 512;
        float hv = d_hcur[n * H_DIM + h];
#pragma unroll
        for (int p = 0; p < 16; ++p) {
            float a = d_Araw[(size_t)(n * 16 + p) * H_DIM + h];
            av[e][p] = a;
            partial[p] += hv * a;
        }
    }
    int lane = tid & 31, warp = tid >> 5;
#pragma unroll
    for (int p = 0; p < 16; ++p) {
        float v = partial[p];
#pragma unroll
        for (int o = 16; o > 0; o >>= 1) v += __shfl_down_sync(0xFFFFFFFFu, v, o);
        if (lane == 0) wsum[warp][p] = v;
    }
    __syncthreads();
    if (tid == 0) {
        float s[16]; float m = -1e30f;
#pragma unroll
        for (int p = 0; p < 16; ++p) {
            float v = 0.f;
            for (int w = 0; w < 16; ++w) v += wsum[w][p];
            v *= 0.03125f;
            s[p] = v;
            m = fmaxf(m, v);
        }
        float tot = 0.f;
#pragma unroll
        for (int p = 0; p < 16; ++p) { s[p] = expf(s[p] - m); tot += s[p]; }
        float inv = 1.f / tot;
#pragma unroll
        for (int p = 0; p < 16; ++p) wsm[p] = s[p] * inv;
    }
    __syncthreads();
    float w[16];
#pragma unroll
    for (int p = 0; p < 16; ++p) w[p] = wsm[p];
#pragma unroll
    for (int e = 0; e < 2; ++e) {
        int h = tid + e * 512;
        float s = 0.f;
#pragma unroll
        for (int p = 0; p < 16; ++p) s += w[p] * av[e][p];
        d_attn[n * H_DIM + h] = s;
    }
}

// fused: LSTM pointwise (h_t, c_t) + attention for step t+1.
// one block per image, 512 threads, each owns 2 h values.
__global__ void lstm_step_fused(int t) {
    const int n = blockIdx.x;
    const int tid = threadIdx.x;
    __shared__ float wsum[16][17];
    __shared__ float wsm[16];

    float hv[2];
#pragma unroll
    for (int e = 0; e < 2; ++e) {
        int h = tid + (e << 9);
        int idx = (n << 10) + h;
        const float* zr = d_z + (size_t)n * Z_DIM;
        float ai = zr[h];
        float af = zr[h + 1024];
        float ao = zr[h + 2048];
        float ag = zr[h + 3072];
        float c  = sigmoidf_(af) * d_ccur[idx] + sigmoidf_(ai) * tanhf(ag);
        float hn = sigmoidf_(ao) * tanhf(c);
        d_ccur[idx] = c;
        d_hcur[idx] = hn;
        d_hs[(size_t)t * (N_IMG * H_DIM) + idx] = hn;
        hv[e] = hn;
    }

    // attention for next step using fresh h (registers)
    float av[2][16];
    float partial[16];
#pragma unroll
    for (int p = 0; p < 16; ++p) partial[p] = 0.f;
#pragma unroll
    for (int e = 0; e < 2; ++e) {
        int h = tid + (e << 9);
#pragma unroll
        for (int p = 0; p < 16; ++p) {
            float a = d_Araw[(size_t)(n * 16 + p) * H_DIM + h];
            av[e][p] = a;
            partial[p] += hv[e] * a;
        }
    }
    int lane = tid & 31, warp = tid >> 5;
#pragma unroll
    for (int p = 0; p < 16; ++p) {
        float v = partial[p];
#pragma unroll
        for (int o = 16; o > 0; o >>= 1) v += __shfl_down_sync(0xFFFFFFFFu, v, o);
        if (lane == 0) wsum[warp][p] = v;
    }
    __syncthreads();
    if (tid == 0) {
        float s[16]; float m = -1e30f;
#pragma unroll
        for (int p = 0; p < 16; ++p) {
            float v = 0.f;
            for (int w = 0; w < 16; ++w) v += wsum[w][p];
            v *= 0.03125f;
            s[p] = v;
            m = fmaxf(m, v);
        }
        float tot = 0.f;
#pragma unroll
        for (int p = 0; p < 16; ++p) { s[p] = expf(s[p] - m); tot += s[p]; }
        float inv = 1.f / tot;
#pragma unroll
        for (int p = 0; p < 16; ++p) wsm[p] = s[p] * inv;
    }
    __syncthreads();
    float w[16];
#pragma unroll
    for (int p = 0; p < 16; ++p) w[p] = wsm[p];
#pragma unroll
    for (int e = 0; e < 2; ++e) {
        int h = tid + (e << 9);
        float s = 0.f;
#pragma unroll
        for (int p = 0; p < 16; ++p) s += w[p] * av[e][p];
        d_attn[n * H_DIM + h] = s;
    }
}

// one block per (t,n) row: streaming logsumexp over V + target score
__global__ void loss_rows(const int* __restrict__ cap) {
    const int r = blockIdx.x;           // r = t*128 + n
    const int t = r >> 7, n = r & 127;
    const int tid = threadIdx.x;
    const int tgt = cap[n * TCAP + t + 1];
    const float* row = d_scores + (size_t)r * V_SIZE;

    __shared__ float sm_t;
    __shared__ float mm[256], ss[256];

    float m = -1e30f, s = 0.f;
    for (int v = tid; v < V_SIZE; v += 256) {
        float x = row[v];
        if (v == tgt) sm_t = x;
        if (x > m) { s = s * expf(m - x) + 1.f; m = x; }
        else       { s += expf(x - m); }
    }
    mm[tid] = m; ss[tid] = s;
    __syncthreads();
    for (int o = 128; o > 0; o >>= 1) {
        if (tid < o) {
            float m2 = mm[tid + o], s2 = ss[tid + o];
            float M = fmaxf(mm[tid], m2);
            ss[tid] = ss[tid] * expf(mm[tid] - M) + s2 * expf(m2 - M);
            mm[tid] = M;
        }
        __syncthreads();
    }
    if (tid == 0) {
        float lse = logf(ss[0]) + mm[0];
        d_nll[r] = (tgt != 0) ? (lse - sm_t) : 0.f;
    }
}

__global__ void loss_final(float* __restrict__ out) {
    const int tid = threadIdx.x;
    __shared__ float sm[256];
    float s = 0.f;
    for (int i = tid; i < TSTEPS * N_IMG; i += 256) s += d_nll[i];
    sm[tid] = s;
    __syncthreads();
    for (int o = 128; o > 0; o >>= 1) {
        if (tid < o) sm[tid] += sm[tid + o];
        __syncthreads();
    }
    if (tid == 0) out[0] = sm[0] / (float)N_IMG;
}

// ---------------- launch ----------------
extern "C" void kernel_launch(void* const* d_in, const int* in_sizes, int n_in,
                              void* d_out, int out_size)
{
    const float* features = (const float*)d_in[0];
    const int*   captions = (const int*)  d_in[1];
    const float* W_embed  = (const float*)d_in[2];
    const float* W_proj   = (const float*)d_in[3];
    const float* b_proj   = (const float*)d_in[4];
    const float* Wx       = (const float*)d_in[5];
    const float* Wh       = (const float*)d_in[6];
    const float* Wattn    = (const float*)d_in[7];
    const float* b        = (const float*)d_in[8];
    const float* W_vocab  = (const float*)d_in[9];
    const float* b_vocab  = (const float*)d_in[10];
    float* out = (float*)d_out;

    float *pAT, *pAraw, *pxbuf, *pzbase, *phcur, *pattn, *pz, *phs, *pscores;
    cudaGetSymbolAddress((void**)&pAT,     d_AT);
    cudaGetSymbolAddress((void**)&pAraw,   d_Araw);
    cudaGetSymbolAddress((void**)&pxbuf,   d_xbuf);
    cudaGetSymbolAddress((void**)&pzbase,  d_zbase);
    cudaGetSymbolAddress((void**)&phcur,   d_hcur);
    cudaGetSymbolAddress((void**)&pattn,   d_attn);
    cudaGetSymbolAddress((void**)&pz,      d_z);
    cudaGetSymbolAddress((void**)&phs,     d_hs);
    cudaGetSymbolAddress((void**)&pscores, d_scores);

    // 1) transpose features -> [2048,400]
    transpose_feat<<<(N_IMG * P_SPAT * D_FEAT + 255) / 256, 256>>>(features);

    // 2) Araw = AT @ W_proj + b_proj   [2048,1024]  (fp32; K=400 not mult of 32)
    gemm64x64<<<dim3(H_DIM / 64, (N_IMG * P_SPAT) / 64), 256>>>(
        pAT, W_proj, b_proj, pAraw, N_IMG * P_SPAT, H_DIM, D_FEAT);

    // 3) h0 = mean over spatial; init h,c
    h0_kernel<<<(N_IMG * H_DIM) / 256, 256>>>();

    // 4) gather embeddings -> xbuf [4096,512]
    gather_embed<<<(TSTEPS * N_IMG * W_EMB + 255) / 256, 256>>>(captions, W_embed);

    // 5) zbase = xbuf @ Wx + b   [4096,4096]  (tf32)
    gemm_tf32<128, 4, 2><<<dim3(Z_DIM / 64, (TSTEPS * N_IMG) / 128), 256>>>(
        pxbuf, Wx, nullptr, nullptr, nullptr, b, pzbase,
        TSTEPS * N_IMG, Z_DIM, W_EMB, 0);

    // 6) recurrence
    attn_kernel<<<N_IMG, 512>>>();
    for (int t = 0; t < TSTEPS; ++t) {
        gemm_tf32<64, 2, 4><<<dim3(Z_DIM / 64, N_IMG / 64), 256>>>(
            phcur, Wh, pattn, Wattn,
            pzbase + (size_t)t * N_IMG * Z_DIM, nullptr, pz,
            N_IMG, Z_DIM, H_DIM, H_DIM);
        lstm_step_fused<<<N_IMG, 512>>>(t);
    }

    // 7) scores = hs @ W_vocab + b_vocab   [4096,10000]  (tf32)
    gemm_tf32<128, 4, 2><<<dim3((V_SIZE + 63) / 64, (TSTEPS * N_IMG) / 128), 256>>>(
        phs, W_vocab, nullptr, nullptr, nullptr, b_vocab, pscores,
        TSTEPS * N_IMG, V_SIZE, H_DIM, 0);

    // 8) loss
    loss_rows<<<TSTEPS * N_IMG, 256>>>(captions);
    loss_final<<<1, 256>>>(out);
}